// round 17
// baseline (speedup 1.0000x reference)
#include <cuda_runtime.h>
#include <cuda_fp16.h>
#include <cstdint>
#include <math.h>

#define B_ROWS 8192
#define D_DIM  4096
#define A_DIM  1024
#define H_DIM  128
#define C_DIM  16

// ---------------------------------------------------------------------------
// Scratch (module-scope device memory; no runtime allocation).
// ---------------------------------------------------------------------------
__device__ float  g_A[(size_t)B_ROWS * D_DIM];      // 128 MB: attention logits
__device__ __half g_X[(size_t)B_ROWS * D_DIM];      // 64 MB : fp16(x), then fp16(weighted)
__device__ __half g_T[B_ROWS * A_DIM];              // 16 MB : fp16(tanh(x@W1+b1))
__device__ __half g_W1t[A_DIM * D_DIM];             // [N,K] = [1024,4096]
__device__ __half g_W2t[D_DIM * A_DIM];             // [4096,1024]
__device__ __half g_Wc1t[H_DIM * D_DIM];            // [128,4096]

// ---------------------------------------------------------------------------
// PTX helpers — baseline (non-'a') instructions only.
// ---------------------------------------------------------------------------
__device__ __forceinline__ uint32_t smem_to_u32(const void* p) {
    uint32_t a;
    asm("{ .reg .u64 t; cvta.to.shared.u64 t, %1; cvt.u32.u64 %0, t; }"
        : "=r"(a) : "l"(p));
    return a;
}

__device__ __forceinline__ void cp16(uint32_t saddr, const void* gaddr) {
    asm volatile("cp.async.cg.shared.global [%0], [%1], 16;"
                 :: "r"(saddr), "l"(gaddr));
}
#define CP_COMMIT()  asm volatile("cp.async.commit_group;" ::: "memory")
#define CP_WAIT(n)   asm volatile("cp.async.wait_group %0;" :: "n"(n) : "memory")

__device__ __forceinline__ void ldsm_x4(uint32_t* r, uint32_t addr) {
    asm volatile("ldmatrix.sync.aligned.m8n8.x4.shared.b16 {%0,%1,%2,%3}, [%4];"
                 : "=r"(r[0]), "=r"(r[1]), "=r"(r[2]), "=r"(r[3]) : "r"(addr));
}

// m16n8k16 fp16 MMA, fp32 accumulate.
__device__ __forceinline__ void mma16816(float* d, const uint32_t* a,
                                         const uint32_t* b) {
    asm volatile(
        "mma.sync.aligned.m16n8k16.row.col.f32.f16.f16.f32 "
        "{%0,%1,%2,%3}, {%4,%5,%6,%7}, {%8,%9}, {%0,%1,%2,%3};"
        : "+f"(d[0]), "+f"(d[1]), "+f"(d[2]), "+f"(d[3])
        : "r"(a[0]), "r"(a[1]), "r"(a[2]), "r"(a[3]), "r"(b[0]), "r"(b[1]));
}

__device__ __forceinline__ uint32_t pack_h2(float a, float b) {
    __half2 h = __floats2half2_rn(a, b);
    return *reinterpret_cast<uint32_t*>(&h);
}

__device__ __forceinline__ float warp_red_max(float v) {
    #pragma unroll
    for (int o = 16; o; o >>= 1)
        v = fmaxf(v, __shfl_xor_sync(0xffffffffu, v, o));
    return v;
}
__device__ __forceinline__ float warp_red_sum(float v) {
    #pragma unroll
    for (int o = 16; o; o >>= 1)
        v += __shfl_xor_sync(0xffffffffu, v, o);
    return v;
}
__device__ __forceinline__ int warp_red_sum_i(int v) {
    #pragma unroll
    for (int o = 16; o; o >>= 1)
        v += __shfl_xor_sync(0xffffffffu, v, o);
    return v;
}

// ---------------------------------------------------------------------------
// Weight prep: W[K,N] fp32 -> [N,K] fp16 (transpose + round).
// ---------------------------------------------------------------------------
__global__ void __launch_bounds__(256)
transpose_half_kernel(const float* __restrict__ W,
                      __half* __restrict__ T,
                      int K, int N)
{
    __shared__ float t[32][33];
    const int n0 = blockIdx.x * 32, k0 = blockIdx.y * 32;
    const int tx = threadIdx.x, ty = threadIdx.y;
    #pragma unroll
    for (int j = ty; j < 32; j += 8)
        t[j][tx] = W[(size_t)(k0 + j) * N + n0 + tx];
    __syncthreads();
    #pragma unroll
    for (int j = ty; j < 32; j += 8)
        T[(size_t)(n0 + j) * K + k0 + tx] = __float2half_rn(t[tx][j]);
}

// ---------------------------------------------------------------------------
// Activation convert: fp32 [M,K] -> fp16 [M,K].
// ---------------------------------------------------------------------------
__global__ void __launch_bounds__(256)
tohalf_kernel(const float4* __restrict__ in, uint2* __restrict__ out, int n4)
{
    int i = blockIdx.x * 256 + threadIdx.x;
    if (i < n4) {
        float4 v = in[i];
        uint2 o;
        o.x = pack_h2(v.x, v.y);
        o.y = pack_h2(v.z, v.w);
        out[i] = o;
    }
}

// ---------------------------------------------------------------------------
// Tensor-core GEMM via mma.sync (fp16, fp32 accum), single-term:
//   C = act( A @ B^T + bias ),  A fp16 [M,K] row-major, B fp16 [N,K] row-major.
// CTA tile BM x 128 (BM = MT*32), BK=64, 8 warps (2m x 4n), warp tile MT*16 x 32.
// cp.async 3-stage pipeline, 144B smem row pitch, single barrier per chunk
// (R16-validated), 2 CTAs/SM.
// MODE: 0 -> fp32 out (Cf), 1 -> fp16 out (Ch),
//       2 -> fused classifier: stage relu(h) tile in smem, multiply by
//            Wc2[128,16] + bc2, write out[M,16] fp32 (requires N == 128).
// ACT: 0=identity, 1=tanh, 2=relu.
// ---------------------------------------------------------------------------
template<int MT, int ACT, int MODE>
__global__ void __launch_bounds__(256)
mma_gemm(const __half* __restrict__ A,
         const __half* __restrict__ B,
         const float* __restrict__ bias,
         float* __restrict__ Cf,
         __half* __restrict__ Ch,
         const float* __restrict__ Wc2,
         const float* __restrict__ bc2,
         int M, int N, int K)
{
    constexpr int BM = MT * 32;
    constexpr int BK = 64;                     // fp16 elems per chunk
    constexpr int PITCH = 144;                 // bytes per smem row (64*2 + 16 pad)
    constexpr uint32_t OFF_B = (uint32_t)BM * PITCH;
    constexpr uint32_t BUFBYTES = OFF_B + 128 * PITCH;
    constexpr int AITER = (BM * 8) / 256;      // 16B transfers per thread (A)
    static_assert((BM * 8) % 256 == 0, "");

    extern __shared__ __align__(128) char smem[];
    const uint32_t sbase = smem_to_u32(smem);

    const int tid    = threadIdx.x;
    const int lane   = tid & 31;
    const int warp   = tid >> 5;
    const int warp_m = warp & 1;               // 2 warps along M
    const int warp_n = warp >> 1;              // 4 warps along N
    const int row0   = blockIdx.y * BM;
    const int col0   = blockIdx.x * 128;
    const int nch    = K / BK;

    float acc[MT][4][4];
    #pragma unroll
    for (int mi = 0; mi < MT; mi++)
        #pragma unroll
        for (int ni = 0; ni < 4; ni++)
            #pragma unroll
            for (int r = 0; r < 4; r++) acc[mi][ni][r] = 0.f;

    // ---- chunk loader (cp.async, 16B transfers); commit done by caller ----
    auto load_chunk = [&](int c, int buf) {
        const uint32_t sb = sbase + (uint32_t)buf * BUFBYTES;
        const int kc = c * BK;
        #pragma unroll
        for (int i = 0; i < AITER; i++) {
            int idx = tid + i * 256;
            int m = idx >> 3, seg = idx & 7;
            const __half* g = A + (size_t)(row0 + m) * K + kc + seg * 8;
            cp16(sb + m * PITCH + seg * 16, g);
        }
        #pragma unroll
        for (int i = 0; i < 4; i++) {
            int idx = tid + i * 256;
            int n = idx >> 3, seg = idx & 7;
            const __half* g = B + (size_t)(col0 + n) * K + kc + seg * 8;
            cp16(sb + OFF_B + n * PITCH + seg * 16, g);
        }
    };

    // Prologue: chunks 0 and 1 in flight (one commit group each).
    load_chunk(0, 0);
    CP_COMMIT();
    if (nch > 1) load_chunk(1, 1);
    CP_COMMIT();

    const int lm = lane & 15, lq = lane >> 4;         // A ldmatrix lane mapping
    const int bmat = lane >> 3, brow = lane & 7;      // B ldmatrix lane mapping

    for (int c = 0; c < nch; ++c) {
        // Chunk c's group is second-newest -> WAIT(1) guarantees it landed.
        CP_WAIT(1);
        __syncthreads();          // publish chunk c; also: all reads of buffer
                                  // (c-1)%3 (== (c+2)%3) finished last iter.
        if (c + 2 < nch) load_chunk(c + 2, (c + 2) % 3);
        CP_COMMIT();              // one group per iter keeps count in lockstep.

        const uint32_t sb = sbase + (uint32_t)(c % 3) * BUFBYTES;
        #pragma unroll
        for (int ks = 0; ks < 4; ks++) {              // four K=16 substeps
            uint32_t aR[MT][4];
            #pragma unroll
            for (int mi = 0; mi < MT; mi++) {
                uint32_t ra = sb +
                    (uint32_t)((warp_m * MT * 16 + mi * 16 + lm) * PITCH +
                               ks * 32 + lq * 16);
                ldsm_x4(aR[mi], ra);
            }
            uint32_t bR[4][2];
            #pragma unroll
            for (int tp = 0; tp < 2; tp++) {
                int t  = tp * 2 + (bmat >> 1);
                int kh = bmat & 1;
                uint32_t rb = sb + OFF_B +
                    (uint32_t)((warp_n * 32 + t * 8 + brow) * PITCH +
                               ks * 32 + kh * 16);
                uint32_t q[4];
                ldsm_x4(q, rb);
                bR[tp*2][0] = q[0]; bR[tp*2][1] = q[1];
                bR[tp*2+1][0] = q[2]; bR[tp*2+1][1] = q[3];
            }
            #pragma unroll
            for (int mi = 0; mi < MT; mi++)
                #pragma unroll
                for (int ni = 0; ni < 4; ni++)
                    mma16816(acc[mi][ni], aR[mi], bR[ni]);
        }
    }

    if (MODE == 2) {
        // ---- fused classifier epilogue (N == 128 == H_DIM) ----
        // Stage relu(h + bias) tile into smem, then out = h @ Wc2 + bc2.
        constexpr int HP = H_DIM + 4;          // fp32 pitch, pad vs bank conflicts
        float* hs = reinterpret_cast<float*>(smem);        // [BM][HP]
        float* wc = hs + BM * HP;                          // [128*16]
        float* bc = wc + H_DIM * C_DIM;                    // [16]

        __syncthreads();          // mainloop smem reads done; safe to overwrite
        #pragma unroll
        for (int mi = 0; mi < MT; mi++) {
            #pragma unroll
            for (int ni = 0; ni < 4; ni++) {
                int rl = warp_m * MT * 16 + mi * 16 + (lane >> 2);
                int cl = warp_n * 32 + ni * 8 + (lane & 3) * 2;
                float b0 = bias[cl], b1 = bias[cl + 1];
                #pragma unroll
                for (int h = 0; h < 2; h++) {
                    hs[(rl + h * 8) * HP + cl]     = fmaxf(acc[mi][ni][2*h+0] + b0, 0.f);
                    hs[(rl + h * 8) * HP + cl + 1] = fmaxf(acc[mi][ni][2*h+1] + b1, 0.f);
                }
            }
        }
        for (int i = tid; i < H_DIM * C_DIM; i += 256) wc[i] = Wc2[i];
        if (tid < C_DIM) bc[tid] = bc2[tid];
        __syncthreads();

        // 512 outputs (BM=32 x 16) -> 2 per thread.
        {
            int r = tid >> 3;                  // 0..31
            int c0 = (tid & 7) * 2;            // 0,2,..,14
            float s0 = bc[c0], s1 = bc[c0 + 1];
            const float* hr = hs + r * HP;
            #pragma unroll 16
            for (int k = 0; k < H_DIM; k++) {
                float hv = hr[k];
                s0 += hv * wc[k * C_DIM + c0];
                s1 += hv * wc[k * C_DIM + c0 + 1];
            }
            float2 o; o.x = s0; o.y = s1;
            *reinterpret_cast<float2*>(&Cf[(size_t)(row0 + r) * C_DIM + c0]) = o;
        }
        return;
    }

    // ---- standard epilogue: bias + activation, fp32 or fp16 output ----
    #pragma unroll
    for (int mi = 0; mi < MT; mi++) {
        #pragma unroll
        for (int ni = 0; ni < 4; ni++) {
            int rbase = row0 + warp_m * MT * 16 + mi * 16 + (lane >> 2);
            int cb    = col0 + warp_n * 32 + ni * 8 + (lane & 3) * 2;
            float b0 = bias[cb], b1 = bias[cb + 1];
            #pragma unroll
            for (int h = 0; h < 2; h++) {
                float v0 = acc[mi][ni][2*h + 0] + b0;
                float v1 = acc[mi][ni][2*h + 1] + b1;
                if (ACT == 1) { v0 = tanhf(v0); v1 = tanhf(v1); }
                if (ACT == 2) { v0 = fmaxf(v0, 0.f); v1 = fmaxf(v1, 0.f); }
                size_t o = (size_t)(rbase + h * 8) * N + cb;
                if (MODE == 1) {
                    *reinterpret_cast<uint32_t*>(&Ch[o]) = pack_h2(v0, v1);
                } else {
                    float2 ov; ov.x = v0; ov.y = v1;
                    *reinterpret_cast<float2*>(&Cf[o]) = ov;
                }
            }
        }
    }
}

// ---------------------------------------------------------------------------
// Fused sparsemax + gating, one block per row. Warp-shuffle reductions.
// Reads logits Z (fp32) and fp16(x) from Wh IN PLACE; writes
// weighted = fp16(x) * sparsemax(Z) back to Wh (GEMM3 input).
// ---------------------------------------------------------------------------
__global__ void __launch_bounds__(256)
sparsemax_gate_kernel(const float* __restrict__ Z, __half* __restrict__ Wh)
{
    __shared__ float z[D_DIM];
    __shared__ float swarp[8];
    __shared__ int   cwarp[8];

    const int tid  = threadIdx.x;
    const int lane = tid & 31;
    const int wid  = tid >> 5;
    const size_t roff = (size_t)blockIdx.x * D_DIM;

    for (int i = tid; i < D_DIM / 4; i += 256)
        reinterpret_cast<float4*>(z)[i] =
            reinterpret_cast<const float4*>(Z + roff)[i];
    __syncthreads();

    float m = -3.402823466e38f;
    for (int i = tid; i < D_DIM; i += 256) m = fmaxf(m, z[i]);
    m = warp_red_max(m);
    if (lane == 0) swarp[wid] = m;
    __syncthreads();
    float tau;
    {
        float m8 = -3.402823466e38f;
        #pragma unroll
        for (int w = 0; w < 8; w++) m8 = fmaxf(m8, swarp[w]);
        tau = m8 - 1.0f;          // f(tau0) >= 0 guaranteed
    }

    for (int it = 0; it < 20; ++it) {
        float s = 0.f; int c = 0;
        for (int i = tid; i < D_DIM; i += 256) {
            float d = z[i] - tau;
            if (d > 0.f) { s += d; c++; }
        }
        s = warp_red_sum(s);
        c = warp_red_sum_i(c);
        __syncthreads();
        if (lane == 0) { swarp[wid] = s; cwarp[wid] = c; }
        __syncthreads();
        float S = 0.f; int C = 0;
        #pragma unroll
        for (int w = 0; w < 8; w++) { S += swarp[w]; C += cwarp[w]; }
        if (C == 0) break;
        float delta = (S - 1.0f) / (float)C;
        tau += delta;
        if (fabsf(delta) <= 1e-7f) break;
    }

    // Gate in place: Wh currently holds fp16(x); each element is read and
    // rewritten by the same thread (no cross-thread hazard).
    uint2* wrow = reinterpret_cast<uint2*>(Wh + roff);
    for (int i = tid; i < D_DIM / 4; i += 256) {
        float4 zv = reinterpret_cast<const float4*>(z)[i];
        uint2 xp = wrow[i];
        __half2 x01 = *reinterpret_cast<__half2*>(&xp.x);
        __half2 x23 = *reinterpret_cast<__half2*>(&xp.y);
        float w0 = __half2float(x01.x) * fmaxf(zv.x - tau, 0.f);
        float w1 = __half2float(x01.y) * fmaxf(zv.y - tau, 0.f);
        float w2 = __half2float(x23.x) * fmaxf(zv.z - tau, 0.f);
        float w3 = __half2float(x23.y) * fmaxf(zv.w - tau, 0.f);
        uint2 o;
        o.x = pack_h2(w0, w1);
        o.y = pack_h2(w2, w3);
        wrow[i] = o;
    }
}

// ---------------------------------------------------------------------------
// Launch sequence (graph-capturable: kernel launches only).
// ---------------------------------------------------------------------------
extern "C" void kernel_launch(void* const* d_in, const int* in_sizes, int n_in,
                              void* d_out, int out_size)
{
    const float* x   = (const float*)d_in[0];
    const float* W1  = (const float*)d_in[1];
    const float* b1  = (const float*)d_in[2];
    const float* W2  = (const float*)d_in[3];
    const float* b2  = (const float*)d_in[4];
    const float* Wc1 = (const float*)d_in[5];
    const float* bc1 = (const float*)d_in[6];
    const float* Wc2 = (const float*)d_in[7];
    const float* bc2 = (const float*)d_in[8];
    float* out = (float*)d_out;
    (void)in_sizes; (void)n_in; (void)out_size;

    float *pA;
    __half *pX, *pT, *pW1t, *pW2t, *pWc1t;
    cudaGetSymbolAddress((void**)&pA,    g_A);
    cudaGetSymbolAddress((void**)&pX,    g_X);
    cudaGetSymbolAddress((void**)&pT,    g_T);
    cudaGetSymbolAddress((void**)&pW1t,  g_W1t);
    cudaGetSymbolAddress((void**)&pW2t,  g_W2t);
    cudaGetSymbolAddress((void**)&pWc1t, g_Wc1t);

    // Dynamic smem.
    // Mainloop: 3 stages * (BM + 128) * 144 bytes.
    // MODE 2 (BM=32) additionally needs (32*132 + 2048 + 16) fp32 = 25152 B,
    // which fits inside the 69120 B mainloop allocation.
    const int SMEM_MT4 = 3 * (128 + 128) * 144;   // 110592 (2 CTAs/SM: 221184)
    const int SMEM_MT1 = 3 * (32 + 128) * 144;    // 69120
    cudaFuncSetAttribute(mma_gemm<4,1,1>, cudaFuncAttributeMaxDynamicSharedMemorySize, SMEM_MT4);
    cudaFuncSetAttribute(mma_gemm<4,0,0>, cudaFuncAttributeMaxDynamicSharedMemorySize, SMEM_MT4);
    cudaFuncSetAttribute(mma_gemm<1,2,2>, cudaFuncAttributeMaxDynamicSharedMemorySize, SMEM_MT1);

    // 0) Weight prep: transpose + fp16 round.
    transpose_half_kernel<<<dim3(A_DIM / 32, D_DIM / 32), dim3(32, 8)>>>(
        W1, pW1t, D_DIM, A_DIM);
    transpose_half_kernel<<<dim3(D_DIM / 32, A_DIM / 32), dim3(32, 8)>>>(
        W2, pW2t, A_DIM, D_DIM);
    transpose_half_kernel<<<dim3(H_DIM / 32, D_DIM / 32), dim3(32, 8)>>>(
        Wc1, pWc1t, D_DIM, H_DIM);

    // 0b) Convert x -> fp16.
    {
        int n4 = B_ROWS * D_DIM / 4;
        tohalf_kernel<<<n4 / 256, 256>>>((const float4*)x, (uint2*)pX, n4);
    }

    // 1) T = tanh(x @ W1 + b1), written as fp16.  [8192,1024], K=4096
    mma_gemm<4,1,1><<<dim3(A_DIM / 128, B_ROWS / 128), 256, SMEM_MT4>>>(
        pX, pW1t, b1, nullptr, pT, nullptr, nullptr, B_ROWS, A_DIM, D_DIM);

    // 2) a = T @ W2 + b2 (fp32)          [8192,4096], K=1024
    mma_gemm<4,0,0><<<dim3(D_DIM / 128, B_ROWS / 128), 256, SMEM_MT4>>>(
        pT, pW2t, b2, pA, nullptr, nullptr, nullptr, B_ROWS, D_DIM, A_DIM);

    // 3) weighted = fp16(x) * sparsemax(a), in place in g_X.
    sparsemax_gate_kernel<<<B_ROWS, 256>>>(pA, pX);

    // 4+5) fused: h = relu(weighted @ Wc1 + bc1); out = h @ Wc2 + bc2.
    //      BM=32 -> 256 CTAs (86% machine fill vs 43% at BM=64).
    mma_gemm<1,2,2><<<dim3(1, B_ROWS / 32), 256, SMEM_MT1>>>(
        pX, pWc1t, bc1, out, nullptr, Wc2, bc2, B_ROWS, H_DIM, D_DIM);
}